// round 4
// baseline (speedup 1.0000x reference)
#include <cuda_runtime.h>
#include <cuda_bf16.h>

#define NN 50000
#define NE 800000
#define IND 128
#define HID 64

// ---------------- scratch (device globals; no runtime allocation) ----------
__device__ int   g_deg_in[NN];
__device__ int   g_deg_out[NN];
__device__ int   g_row_ptr[NN + 1];
__device__ int   g_cursor[NN];
__device__ int   g_esrc[NE];
__device__ float g_din[NN];
__device__ float g_dout[NN];
__device__ float g_bufA[NN * IND];   // 128-dim scratch (scaled in_feat)
__device__ float g_bufB[NN * IND];   // 128-dim scratch (gcn t1)
__device__ float g_h [NN * HID];
__device__ float g_f1[NN * HID];
__device__ float g_f2[NN * HID];
__device__ float g_s [NN * HID];
__device__ float g_z [NN * HID];
__device__ float g_Wa[HID * HID];
__device__ float g_Wb[HID * HID];
__device__ float g_Wc[HID * HID];

// ---------------- graph prep ----------------
__global__ void k_zero_deg() {
    int i = blockIdx.x * blockDim.x + threadIdx.x;
    if (i < NN) { g_deg_in[i] = 0; g_deg_out[i] = 0; }
}

__global__ void k_deg(const int* __restrict__ src, const int* __restrict__ dst) {
    int e = blockIdx.x * blockDim.x + threadIdx.x;
    if (e < NE) {
        atomicAdd(&g_deg_in[dst[e]], 1);
        atomicAdd(&g_deg_out[src[e]], 1);
    }
}

// single-block scan over deg_in -> exclusive prefix (row_ptr) + cursor copy
__global__ void k_scan() {
    __shared__ int sh[1024];
    __shared__ int carry;
    int t = threadIdx.x;
    if (t == 0) carry = 0;
    __syncthreads();
    for (int base = 0; base < NN; base += 1024) {
        int idx = base + t;
        int v = (idx < NN) ? g_deg_in[idx] : 0;
        sh[t] = v;
        __syncthreads();
        for (int off = 1; off < 1024; off <<= 1) {
            int x = (t >= off) ? sh[t - off] : 0;
            __syncthreads();
            sh[t] += x;
            __syncthreads();
        }
        int incl = sh[t];
        if (idx < NN) {
            int excl = carry + incl - v;
            g_row_ptr[idx] = excl;
            g_cursor[idx]  = excl;
        }
        __syncthreads();
        if (t == 0) carry += sh[1023];
        __syncthreads();
    }
    if (t == 0) g_row_ptr[NN] = carry;
}

__global__ void k_deginv() {
    int i = blockIdx.x * blockDim.x + threadIdx.x;
    if (i < NN) {
        g_din[i]  = rsqrtf((float)max(g_deg_in[i], 1));
        g_dout[i] = rsqrtf((float)max(g_deg_out[i], 1));
    }
}

__global__ void k_scatter(const int* __restrict__ src, const int* __restrict__ dst) {
    int e = blockIdx.x * blockDim.x + threadIdx.x;
    if (e < NE) {
        int v = dst[e];
        int pos = atomicAdd(&g_cursor[v], 1);
        g_esrc[pos] = src[e];
    }
}

// Wa = 3*W3_0 ; Wb = -3*W3_0 + 3*W3_1 + W3_3 ; Wc = .75*W3_0 -1.5*W3_1 + .75*W3_2 + W3_4
__global__ void k_wabc(const float* __restrict__ W3) {
    int i = blockIdx.x * blockDim.x + threadIdx.x;
    if (i < HID * HID) {
        int k = i >> 6, c = i & 63;
        float w0 = W3[(k      ) * 64 + c];
        float w1 = W3[(64  + k) * 64 + c];
        float w2 = W3[(128 + k) * 64 + c];
        float w3 = W3[(192 + k) * 64 + c];
        float w4 = W3[(256 + k) * 64 + c];
        g_Wa[i] = 3.0f * w0;
        g_Wb[i] = -3.0f * w0 + 3.0f * w1 + w3;
        g_Wc[i] = 0.75f * w0 - 1.5f * w1 + 0.75f * w2 + w4;
    }
}

// ---------------- elementwise scale: y[v,:] = x[v,:] * s[v] (float4) -------
__global__ void k_scale4(const float4* __restrict__ x, const float* __restrict__ s,
                         float4* __restrict__ y, int dim4) {
    int i = blockIdx.x * blockDim.x + threadIdx.x;
    int total = NN * dim4;
    if (i < total) {
        int v = i / dim4;
        float sc = s[v];
        float4 t = x[i];
        t.x *= sc; t.y *= sc; t.z *= sc; t.w *= sc;
        y[i] = t;
    }
}

// ---------------- spmm (CSR-by-dst segment sum), warp per node -------------
// mode 0: y[v,:] = acc * din[v]
// mode 1: y[v,:] = base[v,:] - acc * din[v]     (Laplacian)
__global__ void k_spmm64(const float* __restrict__ xs, const float* __restrict__ base,
                         float* __restrict__ y, int mode) {
    int w = (blockIdx.x * blockDim.x + threadIdx.x) >> 5;
    int lane = threadIdx.x & 31;
    if (w >= NN) return;
    int beg = g_row_ptr[w], end = g_row_ptr[w + 1];
    float2 acc = make_float2(0.f, 0.f);
    int j = beg;
    if (j < end) {
        int u = g_esrc[j];
        while (true) {
            float2 t = *reinterpret_cast<const float2*>(xs + u * 64 + lane * 2);
            j++;
            int un = (j < end) ? g_esrc[j] : 0;
            acc.x += t.x; acc.y += t.y;
            if (j >= end) break;
            u = un;
        }
    }
    float s = g_din[w];
    float2 r;
    if (mode) {
        float2 b = *reinterpret_cast<const float2*>(base + w * 64 + lane * 2);
        r.x = b.x - acc.x * s;
        r.y = b.y - acc.y * s;
    } else {
        r.x = acc.x * s;
        r.y = acc.y * s;
    }
    *reinterpret_cast<float2*>(y + w * 64 + lane * 2) = r;
}

__global__ void k_spmm128(const float* __restrict__ xs, float* __restrict__ y) {
    int w = (blockIdx.x * blockDim.x + threadIdx.x) >> 5;
    int lane = threadIdx.x & 31;
    if (w >= NN) return;
    int beg = g_row_ptr[w], end = g_row_ptr[w + 1];
    float4 acc = make_float4(0.f, 0.f, 0.f, 0.f);
    int j = beg;
    if (j < end) {
        int u = g_esrc[j];
        while (true) {
            float4 t = *reinterpret_cast<const float4*>(xs + u * 128 + lane * 4);
            j++;
            int un = (j < end) ? g_esrc[j] : 0;
            acc.x += t.x; acc.y += t.y; acc.z += t.z; acc.w += t.w;
            if (j >= end) break;
            u = un;
        }
    }
    float s = g_din[w];
    acc.x *= s; acc.y *= s; acc.z *= s; acc.w *= s;
    *reinterpret_cast<float4*>(y + w * 128 + lane * 4) = acc;
}

// ---------------- fp32 tiled GEMM: C(+)= A[M,K] @ B[K,N] ------------------
// flags: 1 = accumulate into C, 2 = add bias, 4 = relu
#define GF_ACC 1
#define GF_BIAS 2
#define GF_RELU 4
__global__ void k_gemm(const float* __restrict__ A, const float* __restrict__ B,
                       const float* __restrict__ bias, float* __restrict__ C,
                       int M, int K, int N, int flags) {
    __shared__ float As[16][68];
    __shared__ float Bs[16][68];
    int tx = threadIdx.x & 15;
    int ty = threadIdx.x >> 4;
    int rowBase = blockIdx.y * 64;
    int colBase = blockIdx.x * 64;
    float acc[4][4] = {};
    for (int k0 = 0; k0 < K; k0 += 16) {
        #pragma unroll
        for (int l = threadIdx.x; l < 64 * 16; l += 256) {
            int kk = l >> 6, r = l & 63;
            int row = rowBase + r;
            As[kk][r] = (row < M) ? A[(long)row * K + k0 + kk] : 0.f;
        }
        #pragma unroll
        for (int l = threadIdx.x; l < 64 * 16; l += 256) {
            int kk = l >> 6, c = l & 63;
            Bs[kk][c] = B[(long)(k0 + kk) * N + colBase + c];
        }
        __syncthreads();
        #pragma unroll
        for (int kk = 0; kk < 16; kk++) {
            float4 av = *reinterpret_cast<const float4*>(&As[kk][ty * 4]);
            float4 bv = *reinterpret_cast<const float4*>(&Bs[kk][tx * 4]);
            float a[4] = {av.x, av.y, av.z, av.w};
            float b[4] = {bv.x, bv.y, bv.z, bv.w};
            #pragma unroll
            for (int i = 0; i < 4; i++)
                #pragma unroll
                for (int jj = 0; jj < 4; jj++)
                    acc[i][jj] += a[i] * b[jj];
        }
        __syncthreads();
    }
    #pragma unroll
    for (int i = 0; i < 4; i++) {
        int row = rowBase + ty * 4 + i;
        if (row >= M) continue;
        #pragma unroll
        for (int jj = 0; jj < 4; jj++) {
            int col = colBase + tx * 4 + jj;
            float v = acc[i][jj];
            if (flags & GF_ACC)  v += C[(long)row * N + col];
            if (flags & GF_BIAS) v += bias[col];
            if (flags & GF_RELU) v = fmaxf(v, 0.f);
            C[(long)row * N + col] = v;
        }
    }
}

// ---------------- tiny head: out[v,0:2] = z[v,:]@W4 + b4 -------------------
__global__ void k_head(const float* __restrict__ z, const float* __restrict__ W4,
                       const float* __restrict__ b4, float* __restrict__ out) {
    int v = blockIdx.x * blockDim.x + threadIdx.x;
    if (v >= NN) return;
    float a0 = b4[0], a1 = b4[1];
    const float4* zr = reinterpret_cast<const float4*>(z + v * 64);
    #pragma unroll
    for (int q = 0; q < 16; q++) {
        float4 t = zr[q];
        int k = q * 4;
        a0 += t.x * W4[(k + 0) * 2] + t.y * W4[(k + 1) * 2] + t.z * W4[(k + 2) * 2] + t.w * W4[(k + 3) * 2];
        a1 += t.x * W4[(k + 0) * 2 + 1] + t.y * W4[(k + 1) * 2 + 1] + t.z * W4[(k + 2) * 2 + 1] + t.w * W4[(k + 3) * 2 + 1];
    }
    out[v * 2]     = a0;
    out[v * 2 + 1] = a1;
}

// ---------------- launch ----------------
extern "C" void kernel_launch(void* const* d_in, const int* in_sizes, int n_in,
                              void* d_out, int out_size) {
    const float* in_feat = (const float*)d_in[0];
    const int*   src     = (const int*)d_in[1];
    const int*   dst     = (const int*)d_in[2];
    const float* W1 = (const float*)d_in[3];
    const float* b1 = (const float*)d_in[4];
    const float* W2 = (const float*)d_in[5];
    const float* b2 = (const float*)d_in[6];
    const float* W3 = (const float*)d_in[7];
    const float* b3 = (const float*)d_in[8];
    const float* W4 = (const float*)d_in[9];
    const float* b4 = (const float*)d_in[10];
    const float* Wg1 = (const float*)d_in[11];
    const float* bg1 = (const float*)d_in[12];
    const float* Wg2 = (const float*)d_in[13];
    const float* bg2 = (const float*)d_in[14];

    float* out = (float*)d_out;          // [NN,2]
    float* emb = out + NN * 2;           // [NN,128]

    float *p_h, *p_f1, *p_f2, *p_s, *p_z, *p_bufA, *p_bufB, *p_Wa, *p_Wb, *p_Wc, *p_din, *p_dout;
    cudaGetSymbolAddress((void**)&p_h,    g_h);
    cudaGetSymbolAddress((void**)&p_f1,   g_f1);
    cudaGetSymbolAddress((void**)&p_f2,   g_f2);
    cudaGetSymbolAddress((void**)&p_s,    g_s);
    cudaGetSymbolAddress((void**)&p_z,    g_z);
    cudaGetSymbolAddress((void**)&p_bufA, g_bufA);
    cudaGetSymbolAddress((void**)&p_bufB, g_bufB);
    cudaGetSymbolAddress((void**)&p_Wa,   g_Wa);
    cudaGetSymbolAddress((void**)&p_Wb,   g_Wb);
    cudaGetSymbolAddress((void**)&p_Wc,   g_Wc);
    cudaGetSymbolAddress((void**)&p_din,  g_din);
    cudaGetSymbolAddress((void**)&p_dout, g_dout);

    const int TB = 256;
    int nBlkN  = (NN + TB - 1) / TB;
    int nBlkE  = (NE + TB - 1) / TB;
    int spmmBlocks = (NN * 32 + TB - 1) / TB;

    // ---- graph prep ----
    k_zero_deg<<<nBlkN, TB>>>();
    k_deg<<<nBlkE, TB>>>(src, dst);
    k_scan<<<1, 1024>>>();
    k_deginv<<<nBlkN, TB>>>();
    k_scatter<<<nBlkE, TB>>>(src, dst);
    k_wabc<<<16, TB>>>(W3);

    dim3 g64((64 + 63) / 64, (NN + 63) / 64);
    dim3 g128((128 + 63) / 64, (NN + 63) / 64);

    // ---- MLP front end: h = relu(relu(X@W1+b1)@W2+b2) ----
    k_gemm<<<g64, 256>>>(in_feat, W1, b1, p_s, NN, 128, 64, GF_BIAS | GF_RELU);
    k_gemm<<<g64, 256>>>(p_s, W2, b2, p_h, NN, 64, 64, GF_BIAS | GF_RELU);

    // ---- f1 = L h ; f2 = L f1 ----
    k_scale4<<<(NN * 16 + TB - 1) / TB, TB>>>((const float4*)p_h, p_din, (float4*)p_s, 16);
    k_spmm64<<<spmmBlocks, TB>>>(p_s, p_h, p_f1, 1);
    k_scale4<<<(NN * 16 + TB - 1) / TB, TB>>>((const float4*)p_f1, p_din, (float4*)p_s, 16);
    k_spmm64<<<spmmBlocks, TB>>>(p_s, p_f1, p_f2, 1);

    // ---- head: z = relu(h@Wa + f1@Wb + f2@Wc + b3); out = z@W4 + b4 ----
    k_gemm<<<g64, 256>>>(p_h,  p_Wa, nullptr, p_z, NN, 64, 64, 0);
    k_gemm<<<g64, 256>>>(p_f1, p_Wb, nullptr, p_z, NN, 64, 64, GF_ACC);
    k_gemm<<<g64, 256>>>(p_f2, p_Wc, b3,      p_z, NN, 64, 64, GF_ACC | GF_BIAS | GF_RELU);
    k_head<<<nBlkN, TB>>>(p_z, W4, b4, out);

    // ---- GCN branch ----
    k_scale4<<<(NN * 32 + TB - 1) / TB, TB>>>((const float4*)in_feat, p_dout, (float4*)p_bufA, 32);
    k_spmm128<<<spmmBlocks, TB>>>(p_bufA, p_bufB);
    k_gemm<<<g64, 256>>>(p_bufB, Wg1, bg1, p_s, NN, 128, 64, GF_BIAS | GF_RELU);
    k_scale4<<<(NN * 16 + TB - 1) / TB, TB>>>((const float4*)p_s, p_dout, (float4*)p_h, 16);
    k_spmm64<<<spmmBlocks, TB>>>(p_h, nullptr, p_f1, 0);
    k_gemm<<<g128, 256>>>(p_f1, Wg2, bg2, emb, NN, 64, 128, GF_BIAS);
}

// round 5
// speedup vs baseline: 2.0629x; 2.0629x over previous
#include <cuda_runtime.h>
#include <cuda_bf16.h>

#define NN 50000
#define NE 800000
#define IND 128
#define HID 64

// ---------------- scratch (device globals; no runtime allocation) ----------
__device__ int   g_deg_in[NN];
__device__ int   g_deg_out[NN];
__device__ int   g_row_beg[NN];
__device__ int   g_cursor[NN];
__device__ int   g_total;
__device__ int   g_esrc[NE];
__device__ float g_din[NN];
__device__ float g_dout[NN];
__device__ float g_bufB[NN * IND];   // gcn t1 (128-dim)
__device__ float g_h [NN * HID];
__device__ float g_f1[NN * HID];
__device__ float g_f2[NN * HID];
__device__ float g_s [NN * HID];
__device__ float g_Wa[HID * HID];
__device__ float g_Wb[HID * HID];
__device__ float g_Wc[HID * HID];

// ---------------- packed fp32x2 FMA (Blackwell FFMA2) ----------------------
__device__ __forceinline__ float2 f2fma(float2 a, float2 b, float2 c) {
    unsigned long long ua = *reinterpret_cast<unsigned long long*>(&a);
    unsigned long long ub = *reinterpret_cast<unsigned long long*>(&b);
    unsigned long long uc = *reinterpret_cast<unsigned long long*>(&c);
    unsigned long long ud;
    asm("fma.rn.f32x2 %0, %1, %2, %3;" : "=l"(ud) : "l"(ua), "l"(ub), "l"(uc));
    return *reinterpret_cast<float2*>(&ud);
}

// ---------------- graph prep ----------------
__global__ void k_zero_deg() {
    int i = blockIdx.x * blockDim.x + threadIdx.x;
    if (i < NN) { g_deg_in[i] = 0; g_deg_out[i] = 0; }
    if (i == 0) g_total = 0;
}

__global__ void k_deg(const int* __restrict__ src, const int* __restrict__ dst) {
    int e = blockIdx.x * blockDim.x + threadIdx.x;
    if (e < NE) {
        atomicAdd(&g_deg_in[dst[e]], 1);
        atomicAdd(&g_deg_out[src[e]], 1);
    }
}

// segment offsets via atomic allocation (segment order irrelevant) + deg norms
__global__ void k_offsets() {
    int i = blockIdx.x * blockDim.x + threadIdx.x;
    if (i < NN) {
        int d = g_deg_in[i];
        int pos = atomicAdd(&g_total, d);
        g_row_beg[i] = pos;
        g_cursor[i]  = pos;
        g_din[i]  = rsqrtf((float)max(d, 1));
        g_dout[i] = rsqrtf((float)max(g_deg_out[i], 1));
    }
}

__global__ void k_scatter(const int* __restrict__ src, const int* __restrict__ dst) {
    int e = blockIdx.x * blockDim.x + threadIdx.x;
    if (e < NE) {
        int v = dst[e];
        int pos = atomicAdd(&g_cursor[v], 1);
        g_esrc[pos] = src[e];
    }
}

// Wa = 3*W3_0 ; Wb = -3*W3_0 + 3*W3_1 + W3_3 ; Wc = .75*W3_0 -1.5*W3_1 + .75*W3_2 + W3_4
__global__ void k_wabc(const float* __restrict__ W3) {
    int i = blockIdx.x * blockDim.x + threadIdx.x;
    if (i < HID * HID) {
        int k = i >> 6, c = i & 63;
        float w0 = W3[(k      ) * 64 + c];
        float w1 = W3[(64  + k) * 64 + c];
        float w2 = W3[(128 + k) * 64 + c];
        float w3 = W3[(192 + k) * 64 + c];
        float w4 = W3[(256 + k) * 64 + c];
        g_Wa[i] = 3.0f * w0;
        g_Wb[i] = -3.0f * w0 + 3.0f * w1 + w3;
        g_Wc[i] = 0.75f * w0 - 1.5f * w1 + 0.75f * w2 + w4;
    }
}

// ---------------- spmm with fused gather-scale (warp per node) -------------
// acc = sum_{u in N(v)} x[u,:] * gsc[u]
// mode 1: y[v] = base[v] - din[v]*acc     (Laplacian)
// mode 0: y[v] = din[v]*acc               (GCN norm)
__global__ void k_spmm64(const float* __restrict__ x, const float* __restrict__ gsc,
                         const float* __restrict__ base, float* __restrict__ y, int mode) {
    int w = (blockIdx.x * blockDim.x + threadIdx.x) >> 5;
    int lane = threadIdx.x & 31;
    if (w >= NN) return;
    int beg = g_row_beg[w];
    int end = beg + g_deg_in[w];
    float2 acc = make_float2(0.f, 0.f);
    #pragma unroll 4
    for (int j = beg; j < end; j++) {
        int u = g_esrc[j];
        float s = gsc[u];
        float2 t = *reinterpret_cast<const float2*>(x + u * 64 + lane * 2);
        acc.x += t.x * s;
        acc.y += t.y * s;
    }
    float sd = g_din[w];
    float2 r;
    if (mode) {
        float2 b = *reinterpret_cast<const float2*>(base + w * 64 + lane * 2);
        r.x = b.x - acc.x * sd;
        r.y = b.y - acc.y * sd;
    } else {
        r.x = acc.x * sd;
        r.y = acc.y * sd;
    }
    *reinterpret_cast<float2*>(y + w * 64 + lane * 2) = r;
}

__global__ void k_spmm128(const float* __restrict__ x, const float* __restrict__ gsc,
                          float* __restrict__ y) {
    int w = (blockIdx.x * blockDim.x + threadIdx.x) >> 5;
    int lane = threadIdx.x & 31;
    if (w >= NN) return;
    int beg = g_row_beg[w];
    int end = beg + g_deg_in[w];
    float4 acc = make_float4(0.f, 0.f, 0.f, 0.f);
    #pragma unroll 4
    for (int j = beg; j < end; j++) {
        int u = g_esrc[j];
        float s = gsc[u];
        float4 t = *reinterpret_cast<const float4*>(x + u * 128 + lane * 4);
        acc.x += t.x * s; acc.y += t.y * s; acc.z += t.z * s; acc.w += t.w * s;
    }
    float sd = g_din[w];
    acc.x *= sd; acc.y *= sd; acc.z *= sd; acc.w *= sd;
    *reinterpret_cast<float4*>(y + w * 128 + lane * 4) = acc;
}

// ---------------- fp32x2 tiled GEMM: C = epi(A[M,K] @ B[K,N]) --------------
#define GF_BIAS 2
#define GF_RELU 4
#define KT 32

// shared inner-loop macro: consumes As2[64][36] / Bs[32][68] into acc[4][2]
#define GEMM_INNER(As2, Bs, acc, tx, ty)                                     \
    _Pragma("unroll")                                                        \
    for (int kk = 0; kk < KT; kk += 4) {                                     \
        float4 a4[4];                                                        \
        _Pragma("unroll")                                                    \
        for (int i = 0; i < 4; i++)                                          \
            a4[i] = *reinterpret_cast<const float4*>(&As2[ty * 4 + i][kk]);  \
        _Pragma("unroll")                                                    \
        for (int q = 0; q < 4; q++) {                                        \
            float4 bv = *reinterpret_cast<const float4*>(&Bs[kk + q][tx * 4]); \
            float2 b01 = make_float2(bv.x, bv.y);                            \
            float2 b23 = make_float2(bv.z, bv.w);                            \
            _Pragma("unroll")                                                \
            for (int i = 0; i < 4; i++) {                                    \
                float a = (q == 0) ? a4[i].x : (q == 1) ? a4[i].y             \
                        : (q == 2) ? a4[i].z : a4[i].w;                      \
                float2 aa = make_float2(a, a);                               \
                acc[i][0] = f2fma(aa, b01, acc[i][0]);                       \
                acc[i][1] = f2fma(aa, b23, acc[i][1]);                       \
            }                                                                \
        }                                                                    \
    }

__global__ void __launch_bounds__(256)
k_gemm(const float* __restrict__ A, const float* __restrict__ B,
       const float* __restrict__ bias, float* __restrict__ C,
       int M, int K, int N, int flags) {
    __shared__ float As2[64][KT + 4];
    __shared__ float Bs[KT][68];
    int tid = threadIdx.x;
    int tx = tid & 15;
    int ty = tid >> 4;
    int rowBase = blockIdx.y * 64;
    int colBase = blockIdx.x * 64;
    float2 acc[4][2] = {};
    for (int k0 = 0; k0 < K; k0 += KT) {
        // A: 64 rows x 8 float4 (coalesced: consecutive threads -> consecutive k)
        #pragma unroll 2
        for (int l = tid; l < 512; l += 256) {
            int r = l >> 3, ks = (l & 7) << 2;
            int row = rowBase + r;
            float4 v = make_float4(0.f, 0.f, 0.f, 0.f);
            if (row < M) v = *reinterpret_cast<const float4*>(A + (size_t)row * K + k0 + ks);
            *reinterpret_cast<float4*>(&As2[r][ks]) = v;
        }
        // B: KT rows x 16 float4 (coalesced)
        #pragma unroll 2
        for (int l = tid; l < 512; l += 256) {
            int kk = l >> 4, c = (l & 15) << 2;
            *reinterpret_cast<float4*>(&Bs[kk][c]) =
                *reinterpret_cast<const float4*>(B + (size_t)(k0 + kk) * N + colBase + c);
        }
        __syncthreads();
        GEMM_INNER(As2, Bs, acc, tx, ty)
        __syncthreads();
    }
    int col0 = colBase + tx * 4;
    float4 bb = make_float4(0.f, 0.f, 0.f, 0.f);
    if (flags & GF_BIAS) bb = *reinterpret_cast<const float4*>(bias + col0);
    #pragma unroll
    for (int i = 0; i < 4; i++) {
        int row = rowBase + ty * 4 + i;
        if (row >= M) continue;
        float4 v = make_float4(acc[i][0].x + bb.x, acc[i][0].y + bb.y,
                               acc[i][1].x + bb.z, acc[i][1].y + bb.w);
        if (flags & GF_RELU) {
            v.x = fmaxf(v.x, 0.f); v.y = fmaxf(v.y, 0.f);
            v.z = fmaxf(v.z, 0.f); v.w = fmaxf(v.w, 0.f);
        }
        *reinterpret_cast<float4*>(C + (size_t)row * N + col0) = v;
    }
}

// ---------------- fused head: out = relu(h@Wa + f1@Wb + f2@Wc + b3) @ W4 + b4
__global__ void __launch_bounds__(256)
k_head_fused(const float* __restrict__ b3, const float* __restrict__ W4,
             const float* __restrict__ b4, float* __restrict__ out) {
    __shared__ float As2[64][KT + 4];
    __shared__ float Bs[KT][68];
    int tid = threadIdx.x;
    int tx = tid & 15;
    int ty = tid >> 4;
    int rowBase = blockIdx.x * 64;
    float2 acc[4][2] = {};
    const float* Asrc[3] = { g_h, g_f1, g_f2 };
    const float* Bsrc[3] = { g_Wa, g_Wb, g_Wc };
    for (int s3 = 0; s3 < 3; s3++) {
        const float* A = Asrc[s3];
        const float* B = Bsrc[s3];
        for (int k0 = 0; k0 < 64; k0 += KT) {
            #pragma unroll 2
            for (int l = tid; l < 512; l += 256) {
                int r = l >> 3, ks = (l & 7) << 2;
                int row = rowBase + r;
                float4 v = make_float4(0.f, 0.f, 0.f, 0.f);
                if (row < NN) v = *reinterpret_cast<const float4*>(A + (size_t)row * 64 + k0 + ks);
                *reinterpret_cast<float4*>(&As2[r][ks]) = v;
            }
            #pragma unroll 2
            for (int l = tid; l < 512; l += 256) {
                int kk = l >> 4, c = (l & 15) << 2;
                *reinterpret_cast<float4*>(&Bs[kk][c]) =
                    *reinterpret_cast<const float4*>(B + (size_t)(k0 + kk) * 64 + c);
            }
            __syncthreads();
            GEMM_INNER(As2, Bs, acc, tx, ty)
            __syncthreads();
        }
    }
    // epilogue: z = relu(acc + b3), then 64->2 contraction with W4
    int col0 = tx * 4;
    float4 bb = *reinterpret_cast<const float4*>(b3 + col0);
    float w40[4], w41[4];
    #pragma unroll
    for (int jj = 0; jj < 4; jj++) {
        w40[jj] = W4[(col0 + jj) * 2];
        w41[jj] = W4[(col0 + jj) * 2 + 1];
    }
    float o0 = b4[0], o1 = b4[1];
    #pragma unroll
    for (int i = 0; i < 4; i++) {
        float z0 = fmaxf(acc[i][0].x + bb.x, 0.f);
        float z1 = fmaxf(acc[i][0].y + bb.y, 0.f);
        float z2 = fmaxf(acc[i][1].x + bb.z, 0.f);
        float z3 = fmaxf(acc[i][1].y + bb.w, 0.f);
        float p0 = z0 * w40[0] + z1 * w40[1] + z2 * w40[2] + z3 * w40[3];
        float p1 = z0 * w41[0] + z1 * w41[1] + z2 * w41[2] + z3 * w41[3];
        #pragma unroll
        for (int off = 8; off >= 1; off >>= 1) {
            p0 += __shfl_down_sync(0xffffffffu, p0, off, 16);
            p1 += __shfl_down_sync(0xffffffffu, p1, off, 16);
        }
        int row = rowBase + ty * 4 + i;
        if (tx == 0 && row < NN) {
            out[row * 2]     = p0 + o0;
            out[row * 2 + 1] = p1 + o1;
        }
    }
}

// ---------------- launch ----------------
extern "C" void kernel_launch(void* const* d_in, const int* in_sizes, int n_in,
                              void* d_out, int out_size) {
    const float* in_feat = (const float*)d_in[0];
    const int*   src     = (const int*)d_in[1];
    const int*   dst     = (const int*)d_in[2];
    const float* W1 = (const float*)d_in[3];
    const float* b1 = (const float*)d_in[4];
    const float* W2 = (const float*)d_in[5];
    const float* b2 = (const float*)d_in[6];
    const float* W3 = (const float*)d_in[7];
    const float* b3 = (const float*)d_in[8];
    const float* W4 = (const float*)d_in[9];
    const float* b4 = (const float*)d_in[10];
    const float* Wg1 = (const float*)d_in[11];
    const float* bg1 = (const float*)d_in[12];
    const float* Wg2 = (const float*)d_in[13];
    const float* bg2 = (const float*)d_in[14];

    float* out = (float*)d_out;          // [NN,2]
    float* emb = out + NN * 2;           // [NN,128]

    float *p_h, *p_f1, *p_f2, *p_s, *p_bufB, *p_din, *p_dout;
    cudaGetSymbolAddress((void**)&p_h,    g_h);
    cudaGetSymbolAddress((void**)&p_f1,   g_f1);
    cudaGetSymbolAddress((void**)&p_f2,   g_f2);
    cudaGetSymbolAddress((void**)&p_s,    g_s);
    cudaGetSymbolAddress((void**)&p_bufB, g_bufB);
    cudaGetSymbolAddress((void**)&p_din,  g_din);
    cudaGetSymbolAddress((void**)&p_dout, g_dout);

    const int TB = 256;
    int nBlkN = (NN + TB - 1) / TB;
    int nBlkE = (NE + TB - 1) / TB;
    int spmmBlocks = (NN * 32 + TB - 1) / TB;

    // ---- graph prep (no serial scan: atomic segment allocation) ----
    k_zero_deg<<<nBlkN, TB>>>();
    k_deg<<<nBlkE, TB>>>(src, dst);
    k_offsets<<<nBlkN, TB>>>();
    k_scatter<<<nBlkE, TB>>>(src, dst);
    k_wabc<<<16, TB>>>(W3);

    dim3 g64(1, (NN + 63) / 64);
    dim3 g128(2, (NN + 63) / 64);
    int hBlocks = (NN + 63) / 64;

    // ---- MLP front end: h = relu(relu(X@W1+b1)@W2+b2) ----
    k_gemm<<<g64, 256>>>(in_feat, W1, b1, p_s, NN, 128, 64, GF_BIAS | GF_RELU);
    k_gemm<<<g64, 256>>>(p_s, W2, b2, p_h, NN, 64, 64, GF_BIAS | GF_RELU);

    // ---- f1 = L h ; f2 = L f1 (gather-scale fused) ----
    k_spmm64<<<spmmBlocks, TB>>>(p_h,  p_din, p_h,  p_f1, 1);
    k_spmm64<<<spmmBlocks, TB>>>(p_f1, p_din, p_f1, p_f2, 1);

    // ---- fused head: out = relu(h@Wa + f1@Wb + f2@Wc + b3) @ W4 + b4 ----
    k_head_fused<<<hBlocks, 256>>>(b3, W4, b4, out);

    // ---- GCN branch ----
    k_spmm128<<<spmmBlocks, TB>>>(in_feat, p_dout, p_bufB);
    k_gemm<<<g64, 256>>>(p_bufB, Wg1, bg1, p_s, NN, 128, 64, GF_BIAS | GF_RELU);
    k_spmm64<<<spmmBlocks, TB>>>(p_s, p_dout, nullptr, p_f1, 0);
    k_gemm<<<g128, 256>>>(p_f1, Wg2, bg2, emb, NN, 64, 128, GF_BIAS);
}